// round 1
// baseline (speedup 1.0000x reference)
#include <cuda_runtime.h>

#define NN   50000
#define EE   800000
#define FEATD 128
#define EMBD  256
#define HD    4
#define CD    64
#define PEDD  32

// -------- scratch (static device globals; no allocations) --------
__device__ float    g_XP [NN*EMBD];   // x @ W (per layer, reused)
__device__ float    g_H0 [NN*EMBD];   // layer0 output (input to layer1)
__device__ float    g_AGG[NN*EMBD];   // sum(e * xp[src]) per dst
__device__ float    g_PE [NN*PEDD];   // relu(PE@W_peg+b)
__device__ float    g_PE1[NN*PEDD];   // relu(pe@W_u0)  (layer1 dist)
__device__ float    g_PNA[NN*PEDD];   // pe_n chain temp
__device__ float    g_PNB[NN*PEDD];
__device__ float    g_DIST[EE];
__device__ float    g_ALS[NN*HD];
__device__ float    g_ALD[NN*HD];
__device__ unsigned g_M  [NN*HD];     // segment max (ordered-uint encoding)
__device__ float    g_DEN[NN*HD];     // sum of exp

__device__ __forceinline__ float lrelu(float x){ return x > 0.f ? x : 0.2f*x; }
// order-preserving float<->uint for atomicMax over signed floats
__device__ __forceinline__ unsigned fflip(float f){
    unsigned u = __float_as_uint(f);
    return (u & 0x80000000u) ? ~u : (u | 0x80000000u);
}
__device__ __forceinline__ float funflip(unsigned u){
    return (u & 0x80000000u) ? __uint_as_float(u & 0x7FFFFFFFu)
                             : __uint_as_float(~u);
}

// -------- small N x 32 @ 32 x 32 matmul + relu (optional bias) --------
__global__ void smallmm_k(const float* __restrict__ in, const float* __restrict__ W,
                          const float* __restrict__ bias, float* __restrict__ out)
{
    __shared__ float Ws[PEDD*PEDD];
    for (int i = threadIdx.x; i < PEDD*PEDD; i += blockDim.x) Ws[i] = W[i];
    __syncthreads();
    int idx = blockIdx.x*blockDim.x + threadIdx.x;
    if (idx >= NN*PEDD) return;
    int row = idx >> 5, col = idx & 31;
    const float* xr = in + row*PEDD;
    float acc = bias ? bias[col] : 0.f;
    #pragma unroll
    for (int k = 0; k < PEDD; k++) acc = fmaf(xr[k], Ws[k*PEDD+col], acc);
    out[idx] = fmaxf(acc, 0.f);
}

// -------- tiled GEMM: C[M x 256] = A[M x K] * B[K x 256] --------
template<int K>
__global__ void gemm_k(const float* __restrict__ A, const float* __restrict__ B,
                       float* __restrict__ C)
{
    __shared__ float As[16][65];     // [k][m], padded
    __shared__ float Bs[16][64];     // [k][n]
    int row0 = blockIdx.x * 64;
    int col0 = blockIdx.y * 64;
    int tx = threadIdx.x & 15;       // out col group
    int ty = threadIdx.x >> 4;       // out row group
    float acc[4][4] = {};
    for (int k0 = 0; k0 < K; k0 += 16) {
        int acol = threadIdx.x & 15;         // k offset
        int arow = threadIdx.x >> 4;         // 0..15
        #pragma unroll
        for (int r = 0; r < 4; r++) {
            int m = arow + r*16;
            int gr = row0 + m;
            As[acol][m] = (gr < NN) ? A[(long)gr*K + k0 + acol] : 0.f;
        }
        int bn = threadIdx.x & 63;
        int bk = threadIdx.x >> 6;           // 0..3
        #pragma unroll
        for (int r = 0; r < 4; r++)
            Bs[bk + r*4][bn] = B[(k0 + bk + r*4)*EMBD + col0 + bn];
        __syncthreads();
        #pragma unroll
        for (int k = 0; k < 16; k++) {
            float a[4], b[4];
            #pragma unroll
            for (int i = 0; i < 4; i++) a[i] = As[k][ty*4+i];
            #pragma unroll
            for (int j = 0; j < 4; j++) b[j] = Bs[k][tx*4+j];
            #pragma unroll
            for (int i = 0; i < 4; i++)
                #pragma unroll
                for (int j = 0; j < 4; j++)
                    acc[i][j] = fmaf(a[i], b[j], acc[i][j]);
        }
        __syncthreads();
    }
    #pragma unroll
    for (int i = 0; i < 4; i++) {
        int gr = row0 + ty*4 + i;
        if (gr < NN) {
            #pragma unroll
            for (int j = 0; j < 4; j++)
                C[(long)gr*EMBD + col0 + tx*4 + j] = acc[i][j];
        }
    }
}

// -------- per-(node,head) attention coefficients --------
__global__ void heads_k(const float* __restrict__ XP, const float* __restrict__ a_s,
                        const float* __restrict__ a_d)
{
    int idx = blockIdx.x*blockDim.x + threadIdx.x;
    if (idx >= NN*HD) return;
    int n = idx >> 2, h = idx & 3;
    const float* xr = XP + (long)n*EMBD + h*CD;
    const float* as = a_s + h*CD;
    const float* ad = a_d + h*CD;
    float s = 0.f, d = 0.f;
    #pragma unroll
    for (int c = 0; c < CD; c++) {
        float v = xr[c];
        s = fmaf(v, as[c], s);
        d = fmaf(v, ad[c], d);
    }
    g_ALS[idx] = s;
    g_ALD[idx] = d;
}

// -------- per-edge PE distance --------
__global__ void dist_k(const int* __restrict__ ei, const float* __restrict__ pe)
{
    int e = blockIdx.x*blockDim.x + threadIdx.x;
    if (e >= EE) return;
    int s = ei[e], d = ei[EE + e];
    const float4* ps = (const float4*)(pe + (long)s*PEDD);
    const float4* pd = (const float4*)(pe + (long)d*PEDD);
    float acc = 1e-8f;
    #pragma unroll
    for (int i = 0; i < 8; i++) {
        float4 a = ps[i], b = pd[i];
        float dx=a.x-b.x, dy=a.y-b.y, dz=a.z-b.z, dw=a.w-b.w;
        acc += dx*dx + dy*dy + dz*dz + dw*dw;
    }
    g_DIST[e] = sqrtf(acc);
}

// -------- reset per-layer accumulators --------
__global__ void init_k()
{
    int i = blockIdx.x*blockDim.x + threadIdx.x;
    if (i < NN*HD) { g_M[i] = 0x007FFFFFu; /* fflip(-inf) */ g_DEN[i] = 0.f; }
    if (i < NN*EMBD) g_AGG[i] = 0.f;
}

// -------- edge pass 1: segment max of logits --------
__global__ void edge_max_k(const int* __restrict__ ei, const float* __restrict__ w_pe)
{
    int e = blockIdx.x*blockDim.x + threadIdx.x;
    if (e >= EE) return;
    int s = ei[e], d = ei[EE + e];
    float4 as = *(const float4*)(g_ALS + s*HD);
    float4 ad = *(const float4*)(g_ALD + d*HD);
    float dv = g_DIST[e];
    float t0 = lrelu(as.x + ad.x) + dv * w_pe[0];
    float t1 = lrelu(as.y + ad.y) + dv * w_pe[1];
    float t2 = lrelu(as.z + ad.z) + dv * w_pe[2];
    float t3 = lrelu(as.w + ad.w) + dv * w_pe[3];
    unsigned* m = g_M + d*HD;
    atomicMax(m+0, fflip(t0));
    atomicMax(m+1, fflip(t1));
    atomicMax(m+2, fflip(t2));
    atomicMax(m+3, fflip(t3));
}

// -------- edge pass 2: exp + denominator + weighted feature accumulation ----
// one warp per edge; lane l handles features [8l, 8l+8), head = l/8
__global__ void edge_acc_k(const int* __restrict__ ei, const float* __restrict__ w_pe,
                           const float* __restrict__ XP)
{
    int warp = (blockIdx.x*blockDim.x + threadIdx.x) >> 5;
    int lane = threadIdx.x & 31;
    if (warp >= EE) return;
    int e = warp;
    int s = ei[e], d = ei[EE + e];
    int h = lane >> 3;
    float t = lrelu(g_ALS[s*HD + h] + g_ALD[d*HD + h]) + g_DIST[e] * w_pe[h];
    float m = funflip(g_M[d*HD + h]);
    float ev = __expf(t - m);
    if ((lane & 7) == 0) atomicAdd(&g_DEN[d*HD + h], ev);
    const float4* xs = (const float4*)(XP + (long)s*EMBD + lane*8);
    float4 v0 = xs[0], v1 = xs[1];
    float* ag = g_AGG + (long)d*EMBD + lane*8;
    atomicAdd(ag+0, ev*v0.x); atomicAdd(ag+1, ev*v0.y);
    atomicAdd(ag+2, ev*v0.z); atomicAdd(ag+3, ev*v0.w);
    atomicAdd(ag+4, ev*v1.x); atomicAdd(ag+5, ev*v1.y);
    atomicAdd(ag+6, ev*v1.z); atomicAdd(ag+7, ev*v1.w);
}

// -------- per-node normalize (+ optional relu) --------
__global__ void norm_k(float* __restrict__ out, int do_relu)
{
    int i4 = blockIdx.x*blockDim.x + threadIdx.x;   // over NN*EMBD/4 float4s
    if (i4 >= NN*EMBD/4) return;
    int n  = i4 >> 6;          // 64 float4 per row
    int c4 = i4 & 63;
    int h  = c4 >> 4;          // 16 float4 per head
    float inv = 1.f / (g_DEN[n*HD + h] + 1e-16f);
    float4 a = ((const float4*)g_AGG)[i4];
    float4 r = make_float4(a.x*inv, a.y*inv, a.z*inv, a.w*inv);
    if (do_relu) {
        r.x = fmaxf(r.x, 0.f); r.y = fmaxf(r.y, 0.f);
        r.z = fmaxf(r.z, 0.f); r.w = fmaxf(r.w, 0.f);
    }
    ((float4*)out)[i4] = r;
}

// ===================== launch =====================
extern "C" void kernel_launch(void* const* d_in, const int* in_sizes, int n_in,
                              void* d_out, int out_size)
{
    const float* PE       = (const float*)d_in[2];
    const float* PE_noise = (const float*)d_in[3];
    const int*   ei       = (const int*)  d_in[4];
    const float* W_peg    = (const float*)d_in[5];
    const float* b_peg    = (const float*)d_in[6];
    const float* x_masked = (const float*)d_in[1];
    const float* W0       = (const float*)d_in[7];
    const float* a_s0     = (const float*)d_in[8];
    const float* a_d0     = (const float*)d_in[9];
    const float* w_pe0    = (const float*)d_in[10];
    const float* W_u0     = (const float*)d_in[11];
    const float* W1       = (const float*)d_in[12];
    const float* a_s1     = (const float*)d_in[13];
    const float* a_d1     = (const float*)d_in[14];
    const float* w_pe1    = (const float*)d_in[15];
    const float* W_u1     = (const float*)d_in[16];
    float* out = (float*)d_out;              // [0, NN*EMBD) = hm ; then NN*PEDD = pe_n

    float *pXP, *pH0, *pPE, *pPE1, *pPNA, *pPNB;
    cudaGetSymbolAddress((void**)&pXP,  g_XP);
    cudaGetSymbolAddress((void**)&pH0,  g_H0);
    cudaGetSymbolAddress((void**)&pPE,  g_PE);
    cudaGetSymbolAddress((void**)&pPE1, g_PE1);
    cudaGetSymbolAddress((void**)&pPNA, g_PNA);
    cudaGetSymbolAddress((void**)&pPNB, g_PNB);

    const int T = 256;
    int g_small = (NN*PEDD + T-1)/T;
    int g_edge  = (EE + T-1)/T;
    int g_warp  = (EE*32 + T-1)/T;
    int g_init  = (NN*EMBD + T-1)/T;
    int g_nh    = (NN*HD + T-1)/T;
    int g_norm  = (NN*EMBD/4 + T-1)/T;
    dim3 g_gemm((NN + 63)/64, EMBD/64);

    // PE encoder + pe_n chain (independent of GAT) + pe1 for layer-1 dist
    smallmm_k<<<g_small, T>>>(PE,       W_peg, b_peg, pPE);
    smallmm_k<<<g_small, T>>>(PE_noise, W_peg, b_peg, pPNA);
    smallmm_k<<<g_small, T>>>(pPNA, W_u0, nullptr, pPNB);
    smallmm_k<<<g_small, T>>>(pPNB, W_u1, nullptr, out + (long)NN*EMBD);   // pe_n out
    smallmm_k<<<g_small, T>>>(pPE,  W_u0, nullptr, pPE1);

    // ---- layer 0 (masked branch) ----
    gemm_k<FEATD><<<g_gemm, T>>>(x_masked, W0, pXP);
    heads_k<<<g_nh, T>>>(pXP, a_s0, a_d0);
    dist_k<<<g_edge, T>>>(ei, pPE);
    init_k<<<g_init, T>>>();
    edge_max_k<<<g_edge, T>>>(ei, w_pe0);
    edge_acc_k<<<g_warp, T>>>(ei, w_pe0, pXP);
    norm_k<<<g_norm, T>>>(pH0, 1);

    // ---- layer 1 (masked branch) ----
    gemm_k<EMBD><<<g_gemm, T>>>(pH0, W1, pXP);
    heads_k<<<g_nh, T>>>(pXP, a_s1, a_d1);
    dist_k<<<g_edge, T>>>(ei, pPE1);
    init_k<<<g_init, T>>>();
    edge_max_k<<<g_edge, T>>>(ei, w_pe1);
    edge_acc_k<<<g_warp, T>>>(ei, w_pe1, pXP);
    norm_k<<<g_norm, T>>>(out, 0);
}

// round 2
// speedup vs baseline: 5.8552x; 5.8552x over previous
#include <cuda_runtime.h>

#define NN   50000
#define EE   800000
#define FEATD 128
#define EMBD  256
#define HD    4
#define CD    64
#define PEDD  32

// -------- scratch (static device globals; no allocations) --------
__device__ float g_XP [NN*EMBD];     // x @ W (per layer, reused)
__device__ float g_H0 [NN*EMBD];     // layer0 output (input to layer1)
__device__ float g_PE [NN*PEDD];     // relu(PE@W_peg+b)
__device__ float g_PE1[NN*PEDD];     // relu(pe@W_u0) (layer1 dist)
__device__ float g_PNA[NN*PEDD];     // pe_n chain temps
__device__ float g_PNB[NN*PEDD];
__device__ float g_ALS[NN*HD];
__device__ float g_ALD[NN*HD];
// CSR by destination
__device__ int   g_cnt[NN];
__device__ int   g_cur[NN];
__device__ int   g_rowptr[NN+1];
__device__ int   g_esrc [EE];        // src node per CSR slot
__device__ int   g_eslot[EE];        // original edge -> CSR slot
__device__ float g_edist[EE];        // dist per CSR slot

__device__ __forceinline__ float lrelu(float x){ return x > 0.f ? x : 0.2f*x; }

// -------- small N x 32 @ 32 x 32 matmul + relu (optional bias) --------
__global__ void smallmm_k(const float* __restrict__ in, const float* __restrict__ W,
                          const float* __restrict__ bias, float* __restrict__ out)
{
    __shared__ float Ws[PEDD*PEDD];
    for (int i = threadIdx.x; i < PEDD*PEDD; i += blockDim.x) Ws[i] = W[i];
    __syncthreads();
    int idx = blockIdx.x*blockDim.x + threadIdx.x;
    if (idx >= NN*PEDD) return;
    int row = idx >> 5, col = idx & 31;
    const float* xr = in + row*PEDD;
    float acc = bias ? bias[col] : 0.f;
    #pragma unroll
    for (int k = 0; k < PEDD; k++) acc = fmaf(xr[k], Ws[k*PEDD+col], acc);
    out[idx] = fmaxf(acc, 0.f);
}

// -------- tiled GEMM: C[M x 256] = A[M x K] * B[K x 256] --------
template<int K>
__global__ void gemm_k(const float* __restrict__ A, const float* __restrict__ B,
                       float* __restrict__ C)
{
    __shared__ float As[16][65];
    __shared__ float Bs[16][64];
    int row0 = blockIdx.x * 64;
    int col0 = blockIdx.y * 64;
    int tx = threadIdx.x & 15;
    int ty = threadIdx.x >> 4;
    float acc[4][4] = {};
    for (int k0 = 0; k0 < K; k0 += 16) {
        int acol = threadIdx.x & 15;
        int arow = threadIdx.x >> 4;
        #pragma unroll
        for (int r = 0; r < 4; r++) {
            int m = arow + r*16;
            int gr = row0 + m;
            As[acol][m] = (gr < NN) ? A[(long)gr*K + k0 + acol] : 0.f;
        }
        int bn = threadIdx.x & 63;
        int bk = threadIdx.x >> 6;
        #pragma unroll
        for (int r = 0; r < 4; r++)
            Bs[bk + r*4][bn] = B[(k0 + bk + r*4)*EMBD + col0 + bn];
        __syncthreads();
        #pragma unroll
        for (int k = 0; k < 16; k++) {
            float a[4], b[4];
            #pragma unroll
            for (int i = 0; i < 4; i++) a[i] = As[k][ty*4+i];
            #pragma unroll
            for (int j = 0; j < 4; j++) b[j] = Bs[k][tx*4+j];
            #pragma unroll
            for (int i = 0; i < 4; i++)
                #pragma unroll
                for (int j = 0; j < 4; j++)
                    acc[i][j] = fmaf(a[i], b[j], acc[i][j]);
        }
        __syncthreads();
    }
    #pragma unroll
    for (int i = 0; i < 4; i++) {
        int gr = row0 + ty*4 + i;
        if (gr < NN) {
            #pragma unroll
            for (int j = 0; j < 4; j++)
                C[(long)gr*EMBD + col0 + tx*4 + j] = acc[i][j];
        }
    }
}

// -------- per-(node,head) attention coefficients --------
__global__ void heads_k(const float* __restrict__ XP, const float* __restrict__ a_s,
                        const float* __restrict__ a_d)
{
    int idx = blockIdx.x*blockDim.x + threadIdx.x;
    if (idx >= NN*HD) return;
    int n = idx >> 2, h = idx & 3;
    const float* xr = XP + (long)n*EMBD + h*CD;
    const float* as = a_s + h*CD;
    const float* ad = a_d + h*CD;
    float s = 0.f, d = 0.f;
    #pragma unroll
    for (int c = 0; c < CD; c++) {
        float v = xr[c];
        s = fmaf(v, as[c], s);
        d = fmaf(v, ad[c], d);
    }
    g_ALS[idx] = s;
    g_ALD[idx] = d;
}

// ================= CSR build (once per launch) =================
__global__ void zero_k()
{
    int i = blockIdx.x*blockDim.x + threadIdx.x;
    if (i < NN) { g_cnt[i] = 0; g_cur[i] = 0; }
}
__global__ void count_k(const int* __restrict__ ei)
{
    int e = blockIdx.x*blockDim.x + threadIdx.x;
    if (e >= EE) return;
    atomicAdd(&g_cnt[ei[EE + e]], 1);
}
__global__ void scan_k()
{
    __shared__ int sums[1024];
    int t = threadIdx.x;
    const int CH = (NN + 1023) / 1024;
    int beg = t * CH, end = min(beg + CH, NN);
    int s = 0;
    for (int i = beg; i < end; i++) s += g_cnt[i];
    sums[t] = s;
    __syncthreads();
    for (int off = 1; off < 1024; off <<= 1) {
        int v = (t >= off) ? sums[t - off] : 0;
        __syncthreads();
        sums[t] += v;
        __syncthreads();
    }
    int run = (t == 0) ? 0 : sums[t - 1];
    for (int i = beg; i < end; i++) { g_rowptr[i] = run; run += g_cnt[i]; }
    if (t == 1023) g_rowptr[NN] = run;
}
__global__ void scatter_k(const int* __restrict__ ei)
{
    int e = blockIdx.x*blockDim.x + threadIdx.x;
    if (e >= EE) return;
    int s = ei[e], d = ei[EE + e];
    int slot = g_rowptr[d] + atomicAdd(&g_cur[d], 1);
    g_esrc[slot] = s;
    g_eslot[e]  = slot;
}

// -------- per-edge PE distance, scattered to CSR slot --------
__global__ void dist_k(const int* __restrict__ ei, const float* __restrict__ pe)
{
    int e = blockIdx.x*blockDim.x + threadIdx.x;
    if (e >= EE) return;
    int s = ei[e], d = ei[EE + e];
    const float4* ps = (const float4*)(pe + (long)s*PEDD);
    const float4* pd = (const float4*)(pe + (long)d*PEDD);
    float acc = 1e-8f;
    #pragma unroll
    for (int i = 0; i < 8; i++) {
        float4 a = ps[i], b = pd[i];
        float dx=a.x-b.x, dy=a.y-b.y, dz=a.z-b.z, dw=a.w-b.w;
        acc += dx*dx + dy*dy + dz*dz + dw*dw;
    }
    g_edist[g_eslot[e]] = sqrtf(acc);
}

// ======= fused GAT aggregation: warp per dst node, zero atomics =======
// lane l handles features [8l, 8l+8), head = l>>3
__global__ void __launch_bounds__(256)
gat_agg_k(const float* __restrict__ w_pe, const float* __restrict__ XP,
          float* __restrict__ out, int do_relu)
{
    int n    = (blockIdx.x*blockDim.x + threadIdx.x) >> 5;
    int lane = threadIdx.x & 31;
    if (n >= NN) return;
    int beg = g_rowptr[n], end = g_rowptr[n+1];
    int h = lane >> 3;
    float ald = g_ALD[n*HD + h];
    float wp  = w_pe[h];

    // pass 1: segment max for this (node, head)
    float m = -1e30f;
    #pragma unroll 4
    for (int i = beg; i < end; i++) {
        int s = g_esrc[i];
        float t = lrelu(g_ALS[s*HD + h] + ald) + g_edist[i] * wp;
        m = fmaxf(m, t);
    }

    // pass 2: exp + denominator + feature gather/accumulate
    float den = 0.f;
    float a0=0,a1=0,a2=0,a3=0,a4=0,a5=0,a6=0,a7=0;
    #pragma unroll 2
    for (int i = beg; i < end; i++) {
        int s = g_esrc[i];
        float t = lrelu(g_ALS[s*HD + h] + ald) + g_edist[i] * wp;
        float ev = __expf(t - m);
        den += ev;
        const float4* xs = (const float4*)(XP + (long)s*EMBD + lane*8);
        float4 v0 = xs[0], v1 = xs[1];
        a0 = fmaf(ev, v0.x, a0); a1 = fmaf(ev, v0.y, a1);
        a2 = fmaf(ev, v0.z, a2); a3 = fmaf(ev, v0.w, a3);
        a4 = fmaf(ev, v1.x, a4); a5 = fmaf(ev, v1.y, a5);
        a6 = fmaf(ev, v1.z, a6); a7 = fmaf(ev, v1.w, a7);
    }
    float inv = 1.f / (den + 1e-16f);
    float4 r0 = make_float4(a0*inv, a1*inv, a2*inv, a3*inv);
    float4 r1 = make_float4(a4*inv, a5*inv, a6*inv, a7*inv);
    if (do_relu) {
        r0.x=fmaxf(r0.x,0.f); r0.y=fmaxf(r0.y,0.f); r0.z=fmaxf(r0.z,0.f); r0.w=fmaxf(r0.w,0.f);
        r1.x=fmaxf(r1.x,0.f); r1.y=fmaxf(r1.y,0.f); r1.z=fmaxf(r1.z,0.f); r1.w=fmaxf(r1.w,0.f);
    }
    float4* op = (float4*)(out + (long)n*EMBD + lane*8);
    op[0] = r0; op[1] = r1;
}

// ===================== launch =====================
extern "C" void kernel_launch(void* const* d_in, const int* in_sizes, int n_in,
                              void* d_out, int out_size)
{
    const float* x_masked = (const float*)d_in[1];
    const float* PE       = (const float*)d_in[2];
    const float* PE_noise = (const float*)d_in[3];
    const int*   ei       = (const int*)  d_in[4];
    const float* W_peg    = (const float*)d_in[5];
    const float* b_peg    = (const float*)d_in[6];
    const float* W0       = (const float*)d_in[7];
    const float* a_s0     = (const float*)d_in[8];
    const float* a_d0     = (const float*)d_in[9];
    const float* w_pe0    = (const float*)d_in[10];
    const float* W_u0     = (const float*)d_in[11];
    const float* W1       = (const float*)d_in[12];
    const float* a_s1     = (const float*)d_in[13];
    const float* a_d1     = (const float*)d_in[14];
    const float* w_pe1    = (const float*)d_in[15];
    const float* W_u1     = (const float*)d_in[16];
    float* out = (float*)d_out;   // [0, NN*EMBD) = hm ; then NN*PEDD = pe_n

    float *pXP, *pH0, *pPE, *pPE1, *pPNA, *pPNB;
    cudaGetSymbolAddress((void**)&pXP,  g_XP);
    cudaGetSymbolAddress((void**)&pH0,  g_H0);
    cudaGetSymbolAddress((void**)&pPE,  g_PE);
    cudaGetSymbolAddress((void**)&pPE1, g_PE1);
    cudaGetSymbolAddress((void**)&pPNA, g_PNA);
    cudaGetSymbolAddress((void**)&pPNB, g_PNB);

    const int T = 256;
    int g_small = (NN*PEDD + T-1)/T;
    int g_edge  = (EE + T-1)/T;
    int g_node  = (NN + T-1)/T;
    int g_nh    = (NN*HD + T-1)/T;
    int g_agg   = (NN*32 + T-1)/T;
    dim3 g_gemm((NN + 63)/64, EMBD/64);

    // CSR by dst (once)
    zero_k<<<g_node, T>>>();
    count_k<<<g_edge, T>>>(ei);
    scan_k<<<1, 1024>>>();
    scatter_k<<<g_edge, T>>>(ei);

    // PE encoder + pe_n chain + layer-1 dist PE
    smallmm_k<<<g_small, T>>>(PE,       W_peg, b_peg, pPE);
    smallmm_k<<<g_small, T>>>(PE_noise, W_peg, b_peg, pPNA);
    smallmm_k<<<g_small, T>>>(pPNA, W_u0, nullptr, pPNB);
    smallmm_k<<<g_small, T>>>(pPNB, W_u1, nullptr, out + (long)NN*EMBD);  // pe_n out
    smallmm_k<<<g_small, T>>>(pPE,  W_u0, nullptr, pPE1);

    // ---- layer 0 (masked branch) ----
    gemm_k<FEATD><<<g_gemm, T>>>(x_masked, W0, pXP);
    heads_k<<<g_nh, T>>>(pXP, a_s0, a_d0);
    dist_k<<<g_edge, T>>>(ei, pPE);
    gat_agg_k<<<g_agg, T>>>(w_pe0, pXP, pH0, 1);

    // ---- layer 1 (masked branch) ----
    gemm_k<EMBD><<<g_gemm, T>>>(pH0, W1, pXP);
    heads_k<<<g_nh, T>>>(pXP, a_s1, a_d1);
    dist_k<<<g_edge, T>>>(ei, pPE1);
    gat_agg_k<<<g_agg, T>>>(w_pe1, pXP, out, 0);
}

// round 4
// speedup vs baseline: 6.8579x; 1.1713x over previous
#include <cuda_runtime.h>
#include <cstdint>

#define NN   50000
#define EE   800000
#define FEATD 128
#define EMBD  256
#define HD    4
#define CD    64
#define PEDD  32

// ================= scratch (static device globals) =================
__device__ float g_XP [NN*EMBD];
__device__ float g_H0 [NN*EMBD];
__device__ float g_PE [NN*PEDD];
__device__ float g_PE1[NN*PEDD];
__device__ float g_PNA[NN*PEDD];
__device__ float g_PNB[NN*PEDD];
__device__ float g_ALS[NN*HD];
__device__ float g_ALD[NN*HD];
__device__ int   g_cnt[NN];
__device__ int   g_cur[NN];
__device__ int   g_rowptr[NN+1];
__device__ int   g_esrc [EE];
__device__ int   g_eslot[EE];
__device__ float g_logit[EE*HD];      // per (CSR slot, head) attention logit
__device__ float g_Bhi[EMBD*EMBD];    // B split hi, original [k][n] layout
__device__ float g_Blo[EMBD*EMBD];    // B split lo

__device__ __forceinline__ float lrelu(float x){ return x > 0.f ? x : 0.2f*x; }
__device__ __forceinline__ float tf32r(float a){
    uint32_t u; asm("cvt.rna.tf32.f32 %0, %1;" : "=r"(u) : "f"(a));
    return __uint_as_float(u);
}
__device__ __forceinline__ void mma_tf32(float* d, uint32_t a0, uint32_t a1,
                                         uint32_t a2, uint32_t a3,
                                         uint32_t b0, uint32_t b1){
    asm volatile(
        "mma.sync.aligned.m16n8k8.row.col.f32.tf32.tf32.f32 "
        "{%0,%1,%2,%3}, {%4,%5,%6,%7}, {%8,%9}, {%0,%1,%2,%3};"
        : "+f"(d[0]), "+f"(d[1]), "+f"(d[2]), "+f"(d[3])
        : "r"(a0), "r"(a1), "r"(a2), "r"(a3), "r"(b0), "r"(b1));
}

// ================= small N x 32 @ 32 x 32 matmul + relu =================
__global__ void smallmm_k(const float* __restrict__ in, const float* __restrict__ W,
                          const float* __restrict__ bias, float* __restrict__ out)
{
    __shared__ float Ws[PEDD*PEDD];
    for (int i = threadIdx.x; i < PEDD*PEDD; i += blockDim.x) Ws[i] = W[i];
    __syncthreads();
    int idx = blockIdx.x*blockDim.x + threadIdx.x;   // over NN*8
    if (idx >= NN*8) return;
    int row = idx >> 3, cg = (idx & 7) * 4;
    const float4* xr = (const float4*)(in + row*PEDD);
    float a0 = bias ? bias[cg+0] : 0.f;
    float a1 = bias ? bias[cg+1] : 0.f;
    float a2 = bias ? bias[cg+2] : 0.f;
    float a3 = bias ? bias[cg+3] : 0.f;
    #pragma unroll
    for (int q = 0; q < 8; q++) {
        float4 v = xr[q];
        const float* w = Ws + (q*4)*PEDD + cg;
        a0 = fmaf(v.x, w[0*PEDD+0], a0); a1 = fmaf(v.x, w[0*PEDD+1], a1);
        a2 = fmaf(v.x, w[0*PEDD+2], a2); a3 = fmaf(v.x, w[0*PEDD+3], a3);
        a0 = fmaf(v.y, w[1*PEDD+0], a0); a1 = fmaf(v.y, w[1*PEDD+1], a1);
        a2 = fmaf(v.y, w[1*PEDD+2], a2); a3 = fmaf(v.y, w[1*PEDD+3], a3);
        a0 = fmaf(v.z, w[2*PEDD+0], a0); a1 = fmaf(v.z, w[2*PEDD+1], a1);
        a2 = fmaf(v.z, w[2*PEDD+2], a2); a3 = fmaf(v.z, w[2*PEDD+3], a3);
        a0 = fmaf(v.w, w[3*PEDD+0], a0); a1 = fmaf(v.w, w[3*PEDD+1], a1);
        a2 = fmaf(v.w, w[3*PEDD+2], a2); a3 = fmaf(v.w, w[3*PEDD+3], a3);
    }
    float4 r = make_float4(fmaxf(a0,0.f), fmaxf(a1,0.f), fmaxf(a2,0.f), fmaxf(a3,0.f));
    *(float4*)(out + row*PEDD + cg) = r;
}

// ================= B tf32 split (keeps [k][n] layout) =================
template<int K>
__global__ void bsplit_k(const float* __restrict__ B)
{
    int i = blockIdx.x*blockDim.x + threadIdx.x;
    if (i >= K*EMBD) return;
    float v = B[i];
    float hi = tf32r(v);
    g_Bhi[i] = hi;
    g_Blo[i] = tf32r(v - hi);
}

// ======= mma.sync tf32x3 GEMM: C[M x 256] = A[M x K] @ B[K x 256] =======
// CTA: 256 thr = 8 warps; tile 128(m) x 128(n); warp tile 64 x 32; KC=16.
#define AST 20      // A smem row stride (floats) -> conflict-free frag loads
#define BST 132     // B smem row stride
template<int K>
__global__ void __launch_bounds__(256, 1)
gemm_mma(const float* __restrict__ A, float* __restrict__ C)
{
    __shared__ float sAh[128*AST], sAl[128*AST];
    __shared__ float sBh[16*BST],  sBl[16*BST];

    const int tid  = threadIdx.x;
    const int wid  = tid >> 5, lane = tid & 31;
    const int grp  = lane >> 2, thr = lane & 3;
    const int wm   = (wid & 1) * 64;        // warp m offset in tile
    const int wn   = (wid >> 1) * 32;       // warp n offset in tile
    const int row0 = blockIdx.x * 128;
    const int n0   = blockIdx.y * 128;

    float acc[4][4][4];
    #pragma unroll
    for (int i = 0; i < 4; i++)
        #pragma unroll
        for (int j = 0; j < 4; j++)
            #pragma unroll
            for (int q = 0; q < 4; q++) acc[i][j][q] = 0.f;

    for (int k0 = 0; k0 < K; k0 += 16) {
        // ---- stage A chunk 128x16 (split on the fly) ----
        #pragma unroll
        for (int u = 0; u < 2; u++) {
            int i4 = tid*2 + u;             // 0..511
            int r  = i4 >> 2, q = i4 & 3;
            int gr = row0 + r;
            float4 v = (gr < NN) ? *(const float4*)(A + (size_t)gr*K + k0 + q*4)
                                 : make_float4(0.f,0.f,0.f,0.f);
            float4 hi = make_float4(tf32r(v.x), tf32r(v.y), tf32r(v.z), tf32r(v.w));
            float4 lo = make_float4(tf32r(v.x-hi.x), tf32r(v.y-hi.y),
                                    tf32r(v.z-hi.z), tf32r(v.w-hi.w));
            *(float4*)(sAh + r*AST + q*4) = hi;
            *(float4*)(sAl + r*AST + q*4) = lo;
        }
        // ---- stage B chunk 16x128 (pre-split in gmem) ----
        #pragma unroll
        for (int u = 0; u < 2; u++) {
            int i4 = tid*2 + u;
            int r  = i4 >> 5, q = i4 & 31;
            size_t gi = (size_t)(k0 + r)*EMBD + n0 + q*4;
            *(float4*)(sBh + r*BST + q*4) = *(const float4*)(g_Bhi + gi);
            *(float4*)(sBl + r*BST + q*4) = *(const float4*)(g_Blo + gi);
        }
        __syncthreads();

        #pragma unroll
        for (int ks = 0; ks < 2; ks++) {
            int kq = ks*8;
            uint32_t ah[4][4], al[4][4], bh[4][2], bl[4][2];
            #pragma unroll
            for (int i = 0; i < 4; i++) {
                int base = (wm + i*16 + grp)*AST + kq + thr;
                ah[i][0] = __float_as_uint(sAh[base]);
                ah[i][1] = __float_as_uint(sAh[base + 8*AST]);
                ah[i][2] = __float_as_uint(sAh[base + 4]);
                ah[i][3] = __float_as_uint(sAh[base + 8*AST + 4]);
                al[i][0] = __float_as_uint(sAl[base]);
                al[i][1] = __float_as_uint(sAl[base + 8*AST]);
                al[i][2] = __float_as_uint(sAl[base + 4]);
                al[i][3] = __float_as_uint(sAl[base + 8*AST + 4]);
            }
            #pragma unroll
            for (int j = 0; j < 4; j++) {
                int base = (kq + thr)*BST + wn + j*8 + grp;
                bh[j][0] = __float_as_uint(sBh[base]);
                bh[j][1] = __float_as_uint(sBh[base + 4*BST]);
                bl[j][0] = __float_as_uint(sBl[base]);
                bl[j][1] = __float_as_uint(sBl[base + 4*BST]);
            }
            #pragma unroll
            for (int i = 0; i < 4; i++)
                #pragma unroll
                for (int j = 0; j < 4; j++) {
                    mma_tf32(acc[i][j], ah[i][0],ah[i][1],ah[i][2],ah[i][3],
                             bh[j][0], bh[j][1]);
                    mma_tf32(acc[i][j], ah[i][0],ah[i][1],ah[i][2],ah[i][3],
                             bl[j][0], bl[j][1]);
                    mma_tf32(acc[i][j], al[i][0],al[i][1],al[i][2],al[i][3],
                             bh[j][0], bh[j][1]);
                }
        }
        __syncthreads();
    }

    // ---- epilogue ----
    #pragma unroll
    for (int i = 0; i < 4; i++) {
        int gr0 = row0 + wm + i*16 + grp;
        int gr1 = gr0 + 8;
        #pragma unroll
        for (int j = 0; j < 4; j++) {
            int nc = n0 + wn + j*8 + thr*2;
            if (gr0 < NN)
                *(float2*)(C + (size_t)gr0*EMBD + nc) = make_float2(acc[i][j][0], acc[i][j][1]);
            if (gr1 < NN)
                *(float2*)(C + (size_t)gr1*EMBD + nc) = make_float2(acc[i][j][2], acc[i][j][3]);
        }
    }
}

// ================= per-(node,head) attention coefficients =================
__global__ void heads_k(const float* __restrict__ XP, const float* __restrict__ a_s,
                        const float* __restrict__ a_d)
{
    int idx = blockIdx.x*blockDim.x + threadIdx.x;
    if (idx >= NN*HD) return;
    int n = idx >> 2, h = idx & 3;
    const float4* xr = (const float4*)(XP + (size_t)n*EMBD + h*CD);
    const float4* as = (const float4*)(a_s + h*CD);
    const float4* ad = (const float4*)(a_d + h*CD);
    float s = 0.f, d = 0.f;
    #pragma unroll
    for (int c = 0; c < 16; c++) {
        float4 v = xr[c], va = as[c], vd = ad[c];
        s = fmaf(v.x,va.x,s); s = fmaf(v.y,va.y,s); s = fmaf(v.z,va.z,s); s = fmaf(v.w,va.w,s);
        d = fmaf(v.x,vd.x,d); d = fmaf(v.y,vd.y,d); d = fmaf(v.z,vd.z,d); d = fmaf(v.w,vd.w,d);
    }
    g_ALS[idx] = s;
    g_ALD[idx] = d;
}

// ================= CSR build =================
__global__ void zero_k()
{
    int i = blockIdx.x*blockDim.x + threadIdx.x;
    if (i < NN) { g_cnt[i] = 0; g_cur[i] = 0; }
}
__global__ void count_k(const int* __restrict__ ei)
{
    int e = blockIdx.x*blockDim.x + threadIdx.x;
    if (e >= EE) return;
    atomicAdd(&g_cnt[ei[EE + e]], 1);
}
__global__ void scan_k()
{
    __shared__ int sums[1024];
    int t = threadIdx.x;
    const int CH = (NN + 1023) / 1024;
    int beg = t * CH, end = min(beg + CH, NN);
    int s = 0;
    for (int i = beg; i < end; i++) s += g_cnt[i];
    sums[t] = s;
    __syncthreads();
    for (int off = 1; off < 1024; off <<= 1) {
        int v = (t >= off) ? sums[t - off] : 0;
        __syncthreads();
        sums[t] += v;
        __syncthreads();
    }
    int run = (t == 0) ? 0 : sums[t - 1];
    for (int i = beg; i < end; i++) { g_rowptr[i] = run; run += g_cnt[i]; }
    if (t == 1023) g_rowptr[NN] = run;
}
__global__ void scatter_k(const int* __restrict__ ei)
{
    int e = blockIdx.x*blockDim.x + threadIdx.x;
    if (e >= EE) return;
    int s = ei[e], d = ei[EE + e];
    int slot = g_rowptr[d] + atomicAdd(&g_cur[d], 1);
    g_esrc[slot] = s;
    g_eslot[e]  = slot;
}

// ======= per-edge logits (dist + attention), scattered to CSR slot =======
__global__ void logit_k(const int* __restrict__ ei, const float* __restrict__ pe,
                        const float* __restrict__ w_pe)
{
    int e = blockIdx.x*blockDim.x + threadIdx.x;
    if (e >= EE) return;
    int s = ei[e], d = ei[EE + e];
    const float4* ps = (const float4*)(pe + (size_t)s*PEDD);
    const float4* pd = (const float4*)(pe + (size_t)d*PEDD);
    float acc = 1e-8f;
    #pragma unroll
    for (int i = 0; i < 8; i++) {
        float4 a = ps[i], b = pd[i];
        float dx=a.x-b.x, dy=a.y-b.y, dz=a.z-b.z, dw=a.w-b.w;
        acc += dx*dx + dy*dy + dz*dz + dw*dw;
    }
    float dist = sqrtf(acc);
    float4 als = *(const float4*)(g_ALS + s*HD);
    float4 ald = *(const float4*)(g_ALD + d*HD);
    float4 t;
    t.x = lrelu(als.x + ald.x) + dist * w_pe[0];
    t.y = lrelu(als.y + ald.y) + dist * w_pe[1];
    t.z = lrelu(als.z + ald.z) + dist * w_pe[2];
    t.w = lrelu(als.w + ald.w) + dist * w_pe[3];
    *(float4*)(g_logit + (size_t)g_eslot[e]*HD) = t;
}

// ======= fused GAT aggregation: warp per dst node, zero atomics =======
__global__ void __launch_bounds__(256)
gat_agg_k(const float* __restrict__ XP, float* __restrict__ out, int do_relu)
{
    int n    = (blockIdx.x*blockDim.x + threadIdx.x) >> 5;
    int lane = threadIdx.x & 31;
    if (n >= NN) return;
    int beg = g_rowptr[n], end = g_rowptr[n+1];
    int h = lane >> 3;

    // pass 1: segment max
    float m = -1e30f;
    #pragma unroll 4
    for (int i = beg; i < end; i++)
        m = fmaxf(m, g_logit[i*HD + h]);

    // pass 2: exp + den + gather/accumulate
    float den = 0.f;
    float a0=0,a1=0,a2=0,a3=0,a4=0,a5=0,a6=0,a7=0;
    #pragma unroll 2
    for (int i = beg; i < end; i++) {
        int s = g_esrc[i];
        float ev = __expf(g_logit[i*HD + h] - m);
        den += ev;
        const float4* xs = (const float4*)(XP + (size_t)s*EMBD + lane*8);
        float4 v0 = xs[0], v1 = xs[1];
        a0 = fmaf(ev, v0.x, a0); a1 = fmaf(ev, v0.y, a1);
        a2 = fmaf(ev, v0.z, a2); a3 = fmaf(ev, v0.w, a3);
        a4 = fmaf(ev, v1.x, a4); a5 = fmaf(ev, v1.y, a5);
        a6 = fmaf(ev, v1.z, a6); a7 = fmaf(ev, v1.w, a7);
    }
    float inv = 1.f / (den + 1e-16f);
    float4 r0 = make_float4(a0*inv, a1*inv, a2*inv, a3*inv);
    float4 r1 = make_float4(a4*inv, a5*inv, a6*inv, a7*inv);
    if (do_relu) {
        r0.x=fmaxf(r0.x,0.f); r0.y=fmaxf(r0.y,0.f); r0.z=fmaxf(r0.z,0.f); r0.w=fmaxf(r0.w,0.f);
        r1.x=fmaxf(r1.x,0.f); r1.y=fmaxf(r1.y,0.f); r1.z=fmaxf(r1.z,0.f); r1.w=fmaxf(r1.w,0.f);
    }
    float4* op = (float4*)(out + (size_t)n*EMBD + lane*8);
    op[0] = r0; op[1] = r1;
}

// ===================== launch =====================
extern "C" void kernel_launch(void* const* d_in, const int* in_sizes, int n_in,
                              void* d_out, int out_size)
{
    const float* x_masked = (const float*)d_in[1];
    const float* PE       = (const float*)d_in[2];
    const float* PE_noise = (const float*)d_in[3];
    const int*   ei       = (const int*)  d_in[4];
    const float* W_peg    = (const float*)d_in[5];
    const float* b_peg    = (const float*)d_in[6];
    const float* W0       = (const float*)d_in[7];
    const float* a_s0     = (const float*)d_in[8];
    const float* a_d0     = (const float*)d_in[9];
    const float* w_pe0    = (const float*)d_in[10];
    const float* W_u0     = (const float*)d_in[11];
    const float* W1       = (const float*)d_in[12];
    const float* a_s1     = (const float*)d_in[13];
    const float* a_d1     = (const float*)d_in[14];
    const float* w_pe1    = (const float*)d_in[15];
    const float* W_u1     = (const float*)d_in[16];
    float* out = (float*)d_out;   // [0, NN*EMBD) = hm ; then NN*PEDD = pe_n

    float *pXP, *pH0, *pPE, *pPE1, *pPNA, *pPNB;
    cudaGetSymbolAddress((void**)&pXP,  g_XP);
    cudaGetSymbolAddress((void**)&pH0,  g_H0);
    cudaGetSymbolAddress((void**)&pPE,  g_PE);
    cudaGetSymbolAddress((void**)&pPE1, g_PE1);
    cudaGetSymbolAddress((void**)&pPNA, g_PNA);
    cudaGetSymbolAddress((void**)&pPNB, g_PNB);

    const int T = 256;
    int g_small = (NN*8 + T-1)/T;
    int g_edge  = (EE + T-1)/T;
    int g_node  = (NN + T-1)/T;
    int g_nh    = (NN*HD + T-1)/T;
    int g_agg   = (NN*32 + T-1)/T;
    dim3 g_gemm((NN + 127)/128, 2);

    // CSR by dst (once)
    zero_k<<<g_node, T>>>();
    count_k<<<g_edge, T>>>(ei);
    scan_k<<<1, 1024>>>();
    scatter_k<<<g_edge, T>>>(ei);

    // PE encoder + pe_n chain + layer-1 dist PE
    smallmm_k<<<g_small, T>>>(PE,       W_peg, b_peg, pPE);
    smallmm_k<<<g_small, T>>>(PE_noise, W_peg, b_peg, pPNA);
    smallmm_k<<<g_small, T>>>(pPNA, W_u0, nullptr, pPNB);
    smallmm_k<<<g_small, T>>>(pPNB, W_u1, nullptr, out + (size_t)NN*EMBD);  // pe_n out
    smallmm_k<<<g_small, T>>>(pPE,  W_u0, nullptr, pPE1);

    // ---- layer 0 (masked branch) ----
    bsplit_k<FEATD><<<(FEATD*EMBD + T-1)/T, T>>>(W0);
    gemm_mma<FEATD><<<g_gemm, T>>>(x_masked, pXP);
    heads_k<<<g_nh, T>>>(pXP, a_s0, a_d0);
    logit_k<<<g_edge, T>>>(ei, pPE, w_pe0);
    gat_agg_k<<<g_agg, T>>>(pXP, pH0, 1);

    // ---- layer 1 (masked branch) ----
    bsplit_k<EMBD><<<(EMBD*EMBD + T-1)/T, T>>>(W1);
    gemm_mma<EMBD><<<g_gemm, T>>>(pH0, pXP);
    heads_k<<<g_nh, T>>>(pXP, a_s1, a_d1);
    logit_k<<<g_edge, T>>>(ei, pPE1, w_pe1);
    gat_agg_k<<<g_agg, T>>>(pXP, out, 0);
}

// round 5
// speedup vs baseline: 7.8276x; 1.1414x over previous
#include <cuda_runtime.h>
#include <cstdint>

#define NN   50000
#define EE   800000
#define FEATD 128
#define EMBD  256
#define HD    4
#define CD    64
#define PEDD  32

// ================= scratch (static device globals) =================
__device__ float g_XP [NN*EMBD];
__device__ float g_H0 [NN*EMBD];
__device__ float g_PE [NN*PEDD];
__device__ float g_PE1[NN*PEDD];
__device__ float g_ALS[NN*HD];
__device__ float g_ALD[NN*HD];
__device__ int   g_cnt[NN];
__device__ int   g_cur[NN];
__device__ int   g_rowptr[NN+1];
__device__ int   g_esrc [EE];

__device__ __forceinline__ float lrelu(float x){ return x > 0.f ? x : 0.2f*x; }
__device__ __forceinline__ float tf32r(float a){
    uint32_t u; asm("cvt.rna.tf32.f32 %0, %1;" : "=r"(u) : "f"(a));
    return __uint_as_float(u);
}
__device__ __forceinline__ uint32_t smem_u32(const void* p){
    uint32_t a;
    asm("{ .reg .u64 t; cvta.to.shared.u64 t, %1; cvt.u32.u64 %0, t; }" : "=r"(a) : "l"(p));
    return a;
}
__device__ __forceinline__ void cpa16(void* dst, const void* src, bool pred){
    uint32_t d = smem_u32(dst);
    int sz = pred ? 16 : 0;
    asm volatile("cp.async.cg.shared.global [%0], [%1], 16, %2;"
                 :: "r"(d), "l"(src), "r"(sz));
}
__device__ __forceinline__ void mma_tf32(float* d, uint32_t a0, uint32_t a1,
                                         uint32_t a2, uint32_t a3,
                                         uint32_t b0, uint32_t b1){
    asm volatile(
        "mma.sync.aligned.m16n8k8.row.col.f32.tf32.tf32.f32 "
        "{%0,%1,%2,%3}, {%4,%5,%6,%7}, {%8,%9}, {%0,%1,%2,%3};"
        : "+f"(d[0]), "+f"(d[1]), "+f"(d[2]), "+f"(d[3])
        : "r"(a0), "r"(a1), "r"(a2), "r"(a3), "r"(b0), "r"(b1));
}

// ========== fused PE chain: up to 3 stages of (32x32 matmul + relu) ==========
// stage1: relu(in@W1 + b1) -> o1?   stage2: relu(s1@W2) -> o2?   stage3: relu(s2@W3) -> o3?
__global__ void fusedpe_k(const float* __restrict__ in,
                          const float* __restrict__ W1, const float* __restrict__ b1,
                          const float* __restrict__ W2, const float* __restrict__ W3,
                          float* __restrict__ o1, float* __restrict__ o2,
                          float* __restrict__ o3)
{
    __shared__ float Ws1[1024], Ws2[1024], Ws3[1024];
    __shared__ float Xa[8][33], Xb[8][33];
    int tid = threadIdx.x;
    for (int i = tid; i < 1024; i += 256) {
        Ws1[i] = W1[i];
        Ws2[i] = W2[i];
        if (W3) Ws3[i] = W3[i];
    }
    int r = tid >> 5, col = tid & 31;
    int row = blockIdx.x*8 + r;
    Xa[r][col] = in[row*PEDD + col];
    __syncthreads();
    // stage 1
    float acc = b1[col];
    #pragma unroll
    for (int k = 0; k < 32; k++) acc = fmaf(Xa[r][k], Ws1[k*32+col], acc);
    acc = fmaxf(acc, 0.f);
    Xb[r][col] = acc;
    if (o1) o1[row*PEDD + col] = acc;
    __syncthreads();
    // stage 2
    acc = 0.f;
    #pragma unroll
    for (int k = 0; k < 32; k++) acc = fmaf(Xb[r][k], Ws2[k*32+col], acc);
    acc = fmaxf(acc, 0.f);
    if (o2) o2[row*PEDD + col] = acc;
    if (!W3) return;
    Xa[r][col] = acc;
    __syncthreads();
    // stage 3
    acc = 0.f;
    #pragma unroll
    for (int k = 0; k < 32; k++) acc = fmaf(Xa[r][k], Ws3[k*32+col], acc);
    if (o3) o3[row*PEDD + col] = fmaxf(acc, 0.f);
}

// ======= cp.async double-buffered mma.sync tf32x3 GEMM =======
// C[M x 256] = A[M x K] @ B[K x 256];  CTA tile 128x128, warp 64x32, KC=16.
#define AST 20
#define BST 136
template<int K>
__global__ void __launch_bounds__(256, 1)
gemm_mma(const float* __restrict__ A, const float* __restrict__ Bm,
         float* __restrict__ C)
{
    __shared__ float sA[2][128*AST];
    __shared__ float sB[2][16*BST];

    const int tid  = threadIdx.x;
    const int wid  = tid >> 5, lane = tid & 31;
    const int grp  = lane >> 2, thr = lane & 3;
    const int wm   = (wid & 1) * 64;
    const int wn   = (wid >> 1) * 32;
    const int row0 = blockIdx.x * 128;
    const int n0   = blockIdx.y * 128;
    const int NC   = K / 16;

    float acc[4][4][4];
    #pragma unroll
    for (int i = 0; i < 4; i++)
        #pragma unroll
        for (int j = 0; j < 4; j++)
            #pragma unroll
            for (int q = 0; q < 4; q++) acc[i][j][q] = 0.f;

    auto load_chunk = [&](int kc, int b){
        int k0 = kc * 16;
        #pragma unroll
        for (int u = 0; u < 2; u++) {
            int i4 = tid*2 + u, r = i4 >> 2, q = i4 & 3;
            int gr = row0 + r;
            const float* src = A + (size_t)(gr < NN ? gr : NN-1)*K + k0 + q*4;
            cpa16(&sA[b][r*AST + q*4], src, gr < NN);
        }
        #pragma unroll
        for (int u = 0; u < 2; u++) {
            int i4 = tid*2 + u, r = i4 >> 5, q = i4 & 31;
            const float* src = Bm + (size_t)(k0 + r)*EMBD + n0 + q*4;
            cpa16(&sB[b][r*BST + q*4], src, true);
        }
    };

    load_chunk(0, 0);
    asm volatile("cp.async.commit_group;" ::: "memory");

    for (int kc = 0; kc < NC; kc++) {
        if (kc + 1 < NC) {
            load_chunk(kc+1, (kc+1) & 1);
            asm volatile("cp.async.commit_group;" ::: "memory");
            asm volatile("cp.async.wait_group 1;" ::: "memory");
        } else {
            asm volatile("cp.async.wait_group 0;" ::: "memory");
        }
        __syncthreads();
        const float* cA = sA[kc & 1];
        const float* cB = sB[kc & 1];
        #pragma unroll
        for (int ks = 0; ks < 2; ks++) {
            int kq = ks*8;
            uint32_t ah[4][4], al[4][4], bh[4][2], bl[4][2];
            #pragma unroll
            for (int i = 0; i < 4; i++) {
                int base = (wm + i*16 + grp)*AST + kq + thr;
                float r0 = cA[base],           r1 = cA[base + 8*AST];
                float r2 = cA[base + 4],       r3 = cA[base + 8*AST + 4];
                float h0=tf32r(r0), h1=tf32r(r1), h2=tf32r(r2), h3=tf32r(r3);
                ah[i][0]=__float_as_uint(h0); ah[i][1]=__float_as_uint(h1);
                ah[i][2]=__float_as_uint(h2); ah[i][3]=__float_as_uint(h3);
                al[i][0]=__float_as_uint(tf32r(r0-h0));
                al[i][1]=__float_as_uint(tf32r(r1-h1));
                al[i][2]=__float_as_uint(tf32r(r2-h2));
                al[i][3]=__float_as_uint(tf32r(r3-h3));
            }
            #pragma unroll
            for (int j = 0; j < 4; j++) {
                int base = (kq + thr)*BST + wn + j*8 + grp;
                float r0 = cB[base], r1 = cB[base + 4*BST];
                float h0 = tf32r(r0), h1 = tf32r(r1);
                bh[j][0]=__float_as_uint(h0); bh[j][1]=__float_as_uint(h1);
                bl[j][0]=__float_as_uint(tf32r(r0-h0));
                bl[j][1]=__float_as_uint(tf32r(r1-h1));
            }
            #pragma unroll
            for (int i = 0; i < 4; i++)
                #pragma unroll
                for (int j = 0; j < 4; j++) {
                    mma_tf32(acc[i][j], ah[i][0],ah[i][1],ah[i][2],ah[i][3],
                             bh[j][0], bh[j][1]);
                    mma_tf32(acc[i][j], ah[i][0],ah[i][1],ah[i][2],ah[i][3],
                             bl[j][0], bl[j][1]);
                    mma_tf32(acc[i][j], al[i][0],al[i][1],al[i][2],al[i][3],
                             bh[j][0], bh[j][1]);
                }
        }
        __syncthreads();
    }

    #pragma unroll
    for (int i = 0; i < 4; i++) {
        int gr0 = row0 + wm + i*16 + grp;
        int gr1 = gr0 + 8;
        #pragma unroll
        for (int j = 0; j < 4; j++) {
            int nc = n0 + wn + j*8 + thr*2;
            if (gr0 < NN)
                *(float2*)(C + (size_t)gr0*EMBD + nc) = make_float2(acc[i][j][0], acc[i][j][1]);
            if (gr1 < NN)
                *(float2*)(C + (size_t)gr1*EMBD + nc) = make_float2(acc[i][j][2], acc[i][j][3]);
        }
    }
}

// ================= per-(node,head) attention coefficients =================
__global__ void heads_k(const float* __restrict__ XP, const float* __restrict__ a_s,
                        const float* __restrict__ a_d)
{
    int idx = blockIdx.x*blockDim.x + threadIdx.x;
    if (idx >= NN*HD) return;
    int n = idx >> 2, h = idx & 3;
    const float4* xr = (const float4*)(XP + (size_t)n*EMBD + h*CD);
    const float4* as = (const float4*)(a_s + h*CD);
    const float4* ad = (const float4*)(a_d + h*CD);
    float s = 0.f, d = 0.f;
    #pragma unroll
    for (int c = 0; c < 16; c++) {
        float4 v = xr[c], va = as[c], vd = ad[c];
        s = fmaf(v.x,va.x,s); s = fmaf(v.y,va.y,s); s = fmaf(v.z,va.z,s); s = fmaf(v.w,va.w,s);
        d = fmaf(v.x,vd.x,d); d = fmaf(v.y,vd.y,d); d = fmaf(v.z,vd.z,d); d = fmaf(v.w,vd.w,d);
    }
    g_ALS[idx] = s;
    g_ALD[idx] = d;
}

// ================= CSR build =================
__global__ void zero_k()
{
    int i = blockIdx.x*blockDim.x + threadIdx.x;
    if (i < NN) { g_cnt[i] = 0; g_cur[i] = 0; }
}
__global__ void count_k(const int* __restrict__ ei)
{
    int e = blockIdx.x*blockDim.x + threadIdx.x;
    if (e >= EE) return;
    atomicAdd(&g_cnt[ei[EE + e]], 1);
}
__global__ void scan_k()
{
    __shared__ int sums[1024];
    int t = threadIdx.x;
    const int CH = (NN + 1023) / 1024;
    int beg = t * CH, end = min(beg + CH, NN);
    int s = 0;
    for (int i = beg; i < end; i++) s += g_cnt[i];
    sums[t] = s;
    __syncthreads();
    for (int off = 1; off < 1024; off <<= 1) {
        int v = (t >= off) ? sums[t - off] : 0;
        __syncthreads();
        sums[t] += v;
        __syncthreads();
    }
    int run = (t == 0) ? 0 : sums[t - 1];
    for (int i = beg; i < end; i++) { g_rowptr[i] = run; run += g_cnt[i]; }
    if (t == 1023) g_rowptr[NN] = run;
}
__global__ void scatter_k(const int* __restrict__ ei)
{
    int e = blockIdx.x*blockDim.x + threadIdx.x;
    if (e >= EE) return;
    int s = ei[e], d = ei[EE + e];
    int slot = g_rowptr[d] + atomicAdd(&g_cur[d], 1);
    g_esrc[slot] = s;
}

// ======= fused single-pass GAT aggregation (online softmax, inline logits) ===
// warp per dst node; lane l: feature chunk [8l,8l+8), head = l>>3, PE dim = l
__global__ void __launch_bounds__(256)
gat_agg_k(const float* __restrict__ XP, const float* __restrict__ pe,
          const float* __restrict__ w_pe, float* __restrict__ out, int do_relu)
{
    int n    = (blockIdx.x*blockDim.x + threadIdx.x) >> 5;
    int lane = threadIdx.x & 31;
    if (n >= NN) return;
    int beg = g_rowptr[n], end = g_rowptr[n+1];
    int h = lane >> 3;
    float ald  = g_ALD[n*HD + h];
    float wp   = __ldg(w_pe + h);
    float pe_d = pe[n*PEDD + lane];

    float m = -1e30f, den = 0.f;
    float a0=0,a1=0,a2=0,a3=0,a4=0,a5=0,a6=0,a7=0;
    for (int i = beg; i < end; i++) {
        int s = g_esrc[i];
        // cooperative PE distance
        float df = pe[s*PEDD + lane] - pe_d;
        float sq = df*df;
        sq += __shfl_xor_sync(0xffffffffu, sq, 16);
        sq += __shfl_xor_sync(0xffffffffu, sq, 8);
        sq += __shfl_xor_sync(0xffffffffu, sq, 4);
        sq += __shfl_xor_sync(0xffffffffu, sq, 2);
        sq += __shfl_xor_sync(0xffffffffu, sq, 1);
        float dist = sqrtf(sq + 1e-8f);
        float t = lrelu(g_ALS[s*HD + h] + ald) + dist * wp;
        // online softmax with unconditional rescale
        float mn = fmaxf(m, t);
        float c  = __expf(m - mn);
        float ev = __expf(t - mn);
        m = mn;
        den = den*c + ev;
        const float4* xs = (const float4*)(XP + (size_t)s*EMBD + lane*8);
        float4 v0 = xs[0], v1 = xs[1];
        a0 = fmaf(a0, c, ev*v0.x); a1 = fmaf(a1, c, ev*v0.y);
        a2 = fmaf(a2, c, ev*v0.z); a3 = fmaf(a3, c, ev*v0.w);
        a4 = fmaf(a4, c, ev*v1.x); a5 = fmaf(a5, c, ev*v1.y);
        a6 = fmaf(a6, c, ev*v1.z); a7 = fmaf(a7, c, ev*v1.w);
    }
    float inv = 1.f / (den + 1e-16f);
    float4 r0 = make_float4(a0*inv, a1*inv, a2*inv, a3*inv);
    float4 r1 = make_float4(a4*inv, a5*inv, a6*inv, a7*inv);
    if (do_relu) {
        r0.x=fmaxf(r0.x,0.f); r0.y=fmaxf(r0.y,0.f); r0.z=fmaxf(r0.z,0.f); r0.w=fmaxf(r0.w,0.f);
        r1.x=fmaxf(r1.x,0.f); r1.y=fmaxf(r1.y,0.f); r1.z=fmaxf(r1.z,0.f); r1.w=fmaxf(r1.w,0.f);
    }
    float4* op = (float4*)(out + (size_t)n*EMBD + lane*8);
    op[0] = r0; op[1] = r1;
}

// ===================== launch =====================
extern "C" void kernel_launch(void* const* d_in, const int* in_sizes, int n_in,
                              void* d_out, int out_size)
{
    const float* x_masked = (const float*)d_in[1];
    const float* PE       = (const float*)d_in[2];
    const float* PE_noise = (const float*)d_in[3];
    const int*   ei       = (const int*)  d_in[4];
    const float* W_peg    = (const float*)d_in[5];
    const float* b_peg    = (const float*)d_in[6];
    const float* W0       = (const float*)d_in[7];
    const float* a_s0     = (const float*)d_in[8];
    const float* a_d0     = (const float*)d_in[9];
    const float* w_pe0    = (const float*)d_in[10];
    const float* W_u0     = (const float*)d_in[11];
    const float* W1       = (const float*)d_in[12];
    const float* a_s1     = (const float*)d_in[13];
    const float* a_d1     = (const float*)d_in[14];
    const float* w_pe1    = (const float*)d_in[15];
    const float* W_u1     = (const float*)d_in[16];
    float* out = (float*)d_out;   // [0, NN*EMBD) = hm ; then NN*PEDD = pe_n

    float *pXP, *pH0, *pPE, *pPE1;
    cudaGetSymbolAddress((void**)&pXP,  g_XP);
    cudaGetSymbolAddress((void**)&pH0,  g_H0);
    cudaGetSymbolAddress((void**)&pPE,  g_PE);
    cudaGetSymbolAddress((void**)&pPE1, g_PE1);

    const int T = 256;
    int g_edge = (EE + T-1)/T;
    int g_node = (NN + T-1)/T;
    int g_nh   = (NN*HD + T-1)/T;
    int g_agg  = (NN*32 + T-1)/T;
    int g_pe   = NN/8;
    dim3 g_gemm((NN + 127)/128, 2);

    // CSR by dst
    zero_k<<<g_node, T>>>();
    count_k<<<g_edge, T>>>(ei);
    scan_k<<<1, 1024>>>();
    scatter_k<<<g_edge, T>>>(ei);

    // PE chains (fused): noise branch -> pe_n out;  clean branch -> g_PE, g_PE1
    fusedpe_k<<<g_pe, T>>>(PE_noise, W_peg, b_peg, W_u0, W_u1,
                           nullptr, nullptr, out + (size_t)NN*EMBD);
    fusedpe_k<<<g_pe, T>>>(PE, W_peg, b_peg, W_u0, nullptr,
                           pPE, pPE1, nullptr);

    // ---- layer 0 (masked branch) ----
    gemm_mma<FEATD><<<g_gemm, T>>>(x_masked, W0, pXP);
    heads_k<<<g_nh, T>>>(pXP, a_s0, a_d0);
    gat_agg_k<<<g_agg, T>>>(pXP, pPE, w_pe0, pH0, 1);

    // ---- layer 1 (masked branch) ----
    gemm_mma<EMBD><<<g_gemm, T>>>(pH0, W1, pXP);
    heads_k<<<g_nh, T>>>(pXP, a_s1, a_d1);
    gat_agg_k<<<g_agg, T>>>(pXP, pPE1, w_pe1, out, 0);
}